// round 5
// baseline (speedup 1.0000x reference)
#include <cuda_runtime.h>

// RuleGraphConvLayer — GB300 sm_103a, round 5
//
//   x[n] = [feat(81) | G + c*feat*(k>=3)(81) | bagg(22)]  (packed by agg)
//   out[n] = x[n] @ [w_s ; w_n]   (K=184, N=64)
//
// R5: final GEMM re-tiled to 2 threads/node x 2 nodes/thread (16 f32x2 accs
// per node-half => 64 acc regs total, no spill risk, W smem reads amortized
// over 2 nodes). scan2 folded into scan3 (one fewer launch).

#define MAX_NODES 100000
#define MAX_EDGES 800000
#define NF 81
#define NB 22
#define OC 64
#define KTOT 184
#define XP 188     // x row pitch: 752 B, every row 16B-aligned

#define SCAN_T 1024
#define SCAN_E 4
#define SCAN_B (SCAN_T * SCAN_E)

__device__ __align__(16) float g_x[MAX_NODES * XP];
__device__ int g_hist[MAX_NODES];
__device__ int g_start[MAX_NODES + 1];
__device__ int g_cursor[MAX_NODES];
__device__ int g_bsum[64];
__device__ __align__(8) int2 g_sorted[MAX_EDGES];

// ---------------------------------------------------------------------------
__global__ void hist_zero_kernel(int n_nodes) {
    int i = blockIdx.x * blockDim.x + threadIdx.x;
    if (i < n_nodes) g_hist[i] = 0;
}

__global__ void hist_kernel(const int* __restrict__ src, int n_edges) {
    int e = blockIdx.x * blockDim.x + threadIdx.x;
    if (e < n_edges) atomicAdd(&g_hist[src[e]], 1);
}

// per-block exclusive scan over 4096 elems; block totals to g_bsum
__global__ __launch_bounds__(SCAN_T) void scan1_kernel(int n) {
    __shared__ int wsum[32];
    int t = threadIdx.x;
    int base = blockIdx.x * SCAN_B + t * SCAN_E;
    int v[SCAN_E];
    int local = 0;
    #pragma unroll
    for (int j = 0; j < SCAN_E; j++) {
        v[j] = (base + j < n) ? g_hist[base + j] : 0;
        local += v[j];
    }
    int lane = t & 31, w = t >> 5;
    int inc = local;
    #pragma unroll
    for (int d = 1; d < 32; d <<= 1) {
        int x = __shfl_up_sync(0xFFFFFFFF, inc, d);
        if (lane >= d) inc += x;
    }
    if (lane == 31) wsum[w] = inc;
    __syncthreads();
    if (t < 32) {
        int x = wsum[t];
        #pragma unroll
        for (int d = 1; d < 32; d <<= 1) {
            int y = __shfl_up_sync(0xFFFFFFFF, x, d);
            if (t >= d) x += y;
        }
        wsum[t] = x;
    }
    __syncthreads();
    int run = inc - local + ((w > 0) ? wsum[w - 1] : 0);
    #pragma unroll
    for (int j = 0; j < SCAN_E; j++) {
        if (base + j < n) g_start[base + j] = run;
        run += v[j];
    }
    if (t == SCAN_T - 1) g_bsum[blockIdx.x] = run;
}

// scan of block sums (done redundantly per block) + apply offsets + cursors
__global__ __launch_bounds__(256) void scan23_kernel(int n, int n_edges, int nsb) {
    __shared__ int off[32];
    int t = threadIdx.x;
    if (t < 32) {
        int x = (t < nsb) ? g_bsum[t] : 0;
        int inc = x;
        #pragma unroll
        for (int d = 1; d < 32; d <<= 1) {
            int y = __shfl_up_sync(0xFFFFFFFF, inc, d);
            if (t >= d) inc += y;
        }
        off[t] = inc - x;   // exclusive
    }
    __syncthreads();
    int i = blockIdx.x * 256 + t;
    if (i < n) {
        int v = g_start[i] + off[i / SCAN_B];
        g_start[i] = v;
        g_cursor[i] = v;
    }
    if (i == 0) g_start[n] = n_edges;
}

__global__ void scatter_kernel(const int* __restrict__ src,
                               const int* __restrict__ dst,
                               int n_edges) {
    int e = blockIdx.x * blockDim.x + threadIdx.x;
    if (e >= n_edges) return;
    int s = src[e];
    int pos = atomicAdd(&g_cursor[s], 1);
    g_sorted[pos] = make_int2(dst[e], e);
}

// ---------------------------------------------------------------------------
// agg: warp per node; gathers feat[dst]/bond, reduces in registers, writes the
// fully-packed x row. 2-edge software pipeline.
// ---------------------------------------------------------------------------
__global__ __launch_bounds__(256) void agg_kernel(
    const float* __restrict__ feat,
    const float* __restrict__ bond,
    int n_nodes) {

    int n = (int)((blockIdx.x * 256 + threadIdx.x) >> 5);
    int lane = threadIdx.x & 31;
    if (n >= n_nodes) return;

    int beg = __ldg(g_start + n);
    int end = __ldg(g_start + n + 1);

    const float* fs = feat + (size_t)n * NF;
    bool has2 = (lane < NF - 64);   // lane < 17
    bool hasb = (lane < NB);
    float f0 = __ldg(fs + lane);
    float f1 = __ldg(fs + lane + 32);
    float f2 = has2 ? __ldg(fs + lane + 64) : 0.f;
    float fs0 = __shfl_sync(0xFFFFFFFF, f0, 0);
    float fs1 = __shfl_sync(0xFFFFFFFF, f0, 1);
    float fs2 = __shfl_sync(0xFFFFFFFF, f0, 2);

    float a0 = 0.f, a1 = 0.f, a2 = 0.f, ab = 0.f, ac = 0.f;

    int i = beg;
    for (; i + 1 < end; i += 2) {
        int2 p0 = __ldg(g_sorted + i);
        int2 p1 = __ldg(g_sorted + i + 1);
        const float* fdA = feat + (size_t)p0.x * NF;
        const float* fdB = feat + (size_t)p1.x * NF;
        float u0 = __ldg(fdA + lane);
        float w0 = __ldg(fdB + lane);
        float u1 = __ldg(fdA + lane + 32);
        float w1 = __ldg(fdB + lane + 32);
        float u2 = has2 ? __ldg(fdA + lane + 64) : 0.f;
        float w2 = has2 ? __ldg(fdB + lane + 64) : 0.f;
        float bu = hasb ? __ldg(bond + (size_t)p0.y * NB + lane) : 0.f;
        float bw = hasb ? __ldg(bond + (size_t)p1.y * NB + lane) : 0.f;

        float dxA = fs0 - __shfl_sync(0xFFFFFFFF, u0, 0);
        float dyA = fs1 - __shfl_sync(0xFFFFFFFF, u0, 1);
        float dzA = fs2 - __shfl_sync(0xFFFFFFFF, u0, 2);
        float ddA = dxA * dxA + dyA * dyA + dzA * dzA;
        float sA = (ddA > 0.f) ? (1.f / ddA) : 10000.f;

        float dxB = fs0 - __shfl_sync(0xFFFFFFFF, w0, 0);
        float dyB = fs1 - __shfl_sync(0xFFFFFFFF, w0, 1);
        float dzB = fs2 - __shfl_sync(0xFFFFFFFF, w0, 2);
        float ddB = dxB * dxB + dyB * dyB + dzB * dzB;
        float sB = (ddB > 0.f) ? (1.f / ddB) : 10000.f;

        a0 += sA * u0 + sB * w0;
        a1 += sA * u1 + sB * w1;
        a2 += sA * u2 + sB * w2;
        ab += bu + bw;
        ac += sA + sB;
    }
    if (i < end) {
        int2 p0 = __ldg(g_sorted + i);
        const float* fdA = feat + (size_t)p0.x * NF;
        float u0 = __ldg(fdA + lane);
        float u1 = __ldg(fdA + lane + 32);
        float u2 = has2 ? __ldg(fdA + lane + 64) : 0.f;
        float bu = hasb ? __ldg(bond + (size_t)p0.y * NB + lane) : 0.f;
        float dxA = fs0 - __shfl_sync(0xFFFFFFFF, u0, 0);
        float dyA = fs1 - __shfl_sync(0xFFFFFFFF, u0, 1);
        float dzA = fs2 - __shfl_sync(0xFFFFFFFF, u0, 2);
        float ddA = dxA * dxA + dyA * dyA + dzA * dzA;
        float sA = (ddA > 0.f) ? (1.f / ddA) : 10000.f;
        a0 += sA * u0;
        a1 += sA * u1;
        a2 += sA * u2;
        ab += bu;
        ac += sA;
    }

    float* xr = g_x + (size_t)n * XP;
    xr[lane] = f0;
    xr[lane + 32] = f1;
    if (has2) xr[lane + 64] = f2;
    xr[NF + lane]      = (lane >= 3) ? (a0 + ac * f0) : a0;
    xr[NF + lane + 32] = a1 + ac * f1;
    if (has2) xr[NF + lane + 64] = a2 + ac * f2;
    if (hasb) xr[2 * NF + lane] = ab;
}

// ---------------------------------------------------------------------------
// final GEMM: 2 threads per node (32 ch each), 2 nodes per thread.
// acc = 2 x 16 packed f32x2 (64 regs). W broadcast from smem, FFMA2.
// ---------------------------------------------------------------------------
__device__ __forceinline__ void fma2_half(unsigned long long* acc,
                                          const ulonglong2* w2, float xv) {
    unsigned long long xx;
    asm("mov.b64 %0, {%1, %1};" : "=l"(xx) : "f"(xv));
    #pragma unroll
    for (int j = 0; j < 8; j++) {
        ulonglong2 wv = w2[j];
        asm("fma.rn.f32x2 %0, %1, %2, %0;" : "+l"(acc[2 * j + 0]) : "l"(xx), "l"(wv.x));
        asm("fma.rn.f32x2 %0, %1, %2, %0;" : "+l"(acc[2 * j + 1]) : "l"(xx), "l"(wv.y));
    }
}

__device__ __forceinline__ void fma2_pair(unsigned long long* acc0,
                                          unsigned long long* acc1,
                                          const ulonglong2* w2,
                                          float xa, float xb) {
    unsigned long long xxa, xxb;
    asm("mov.b64 %0, {%1, %1};" : "=l"(xxa) : "f"(xa));
    asm("mov.b64 %0, {%1, %1};" : "=l"(xxb) : "f"(xb));
    #pragma unroll
    for (int j = 0; j < 8; j++) {
        ulonglong2 wv = w2[j];
        asm("fma.rn.f32x2 %0, %1, %2, %0;" : "+l"(acc0[2 * j + 0]) : "l"(xxa), "l"(wv.x));
        asm("fma.rn.f32x2 %0, %1, %2, %0;" : "+l"(acc1[2 * j + 0]) : "l"(xxb), "l"(wv.x));
        asm("fma.rn.f32x2 %0, %1, %2, %0;" : "+l"(acc0[2 * j + 1]) : "l"(xxa), "l"(wv.y));
        asm("fma.rn.f32x2 %0, %1, %2, %0;" : "+l"(acc1[2 * j + 1]) : "l"(xxb), "l"(wv.y));
    }
}

__global__ __launch_bounds__(256) void final_kernel(
    const float* __restrict__ w_s,   // [81][64]
    const float* __restrict__ w_n,   // [103][64]
    float* __restrict__ out,         // [n_nodes][64]
    int n_nodes) {

    __shared__ __align__(16) float Wsh[KTOT * OC];   // 47104 B

    int t = threadIdx.x;

    #pragma unroll
    for (int r = 0; r < 46; r++) {                   // 46*256 == 184*64
        int idx = r * 256 + t;
        int k = idx >> 6;
        int c = idx & (OC - 1);
        Wsh[idx] = (k < NF) ? __ldg(w_s + k * OC + c)
                            : __ldg(w_n + (k - NF) * OC + c);
    }
    __syncthreads();

    int half = t & 1;                 // channel half: [half*32, half*32+32)
    int pr = t >> 1;                  // node pair index within block
    int n0 = blockIdx.x * 256 + pr * 2;
    int n1 = n0 + 1;
    if (n0 >= n_nodes) return;
    bool v1 = (n1 < n_nodes);

    const float4* x0 = reinterpret_cast<const float4*>(g_x + (size_t)n0 * XP);
    const float4* x1 = reinterpret_cast<const float4*>(
        g_x + (size_t)(v1 ? n1 : n0) * XP);

    unsigned long long acc0[16], acc1[16];
    #pragma unroll
    for (int j = 0; j < 16; j++) { acc0[j] = 0ull; acc1[j] = 0ull; }

    const float* wbase = Wsh + half * 32;

    float4 xa = __ldg(x0);
    float4 xb = __ldg(x1);
    #pragma unroll 2
    for (int k4 = 0; k4 < 46; k4++) {
        float4 ca = xa, cb = xb;
        if (k4 + 1 < 46) { xa = __ldg(x0 + k4 + 1); xb = __ldg(x1 + k4 + 1); }
        const ulonglong2* w2 = reinterpret_cast<const ulonglong2*>(
            wbase + (k4 * 4) * OC);
        fma2_pair(acc0, acc1, w2,                 ca.x, cb.x);
        fma2_pair(acc0, acc1, w2 + (OC >> 2),     ca.y, cb.y);
        fma2_pair(acc0, acc1, w2 + 2 * (OC >> 2), ca.z, cb.z);
        fma2_pair(acc0, acc1, w2 + 3 * (OC >> 2), ca.w, cb.w);
    }

    // store: 32 channels at column offset half*32 for each node
    float* o0 = out + (size_t)n0 * OC + half * 32;
    #pragma unroll
    for (int j = 0; j < 8; j++) {
        float p0, p1, p2, p3;
        asm("mov.b64 {%0, %1}, %2;" : "=f"(p0), "=f"(p1) : "l"(acc0[2 * j + 0]));
        asm("mov.b64 {%0, %1}, %2;" : "=f"(p2), "=f"(p3) : "l"(acc0[2 * j + 1]));
        reinterpret_cast<float4*>(o0)[j] = make_float4(p0, p1, p2, p3);
    }
    if (v1) {
        float* o1 = out + (size_t)n1 * OC + half * 32;
        #pragma unroll
        for (int j = 0; j < 8; j++) {
            float p0, p1, p2, p3;
            asm("mov.b64 {%0, %1}, %2;" : "=f"(p0), "=f"(p1) : "l"(acc1[2 * j + 0]));
            asm("mov.b64 {%0, %1}, %2;" : "=f"(p2), "=f"(p3) : "l"(acc1[2 * j + 1]));
            reinterpret_cast<float4*>(o1)[j] = make_float4(p0, p1, p2, p3);
        }
    }
}

// ---------------------------------------------------------------------------
extern "C" void kernel_launch(void* const* d_in, const int* in_sizes, int n_in,
                              void* d_out, int out_size) {
    const float* feat = (const float*)d_in[0];
    const float* bond = (const float*)d_in[1];
    const float* w_s  = (const float*)d_in[2];
    const float* w_n  = (const float*)d_in[3];
    const int*   src  = (const int*)d_in[4];
    const int*   dst  = (const int*)d_in[5];
    float* out = (float*)d_out;

    int n_nodes = in_sizes[0] / NF;
    int n_edges = in_sizes[4];
    int nsb = (n_nodes + SCAN_B - 1) / SCAN_B;   // 25 for 100K

    hist_zero_kernel<<<(n_nodes + 255) / 256, 256>>>(n_nodes);
    hist_kernel<<<(n_edges + 255) / 256, 256>>>(src, n_edges);
    scan1_kernel<<<nsb, SCAN_T>>>(n_nodes);
    scan23_kernel<<<(n_nodes + 255) / 256, 256>>>(n_nodes, n_edges, nsb);
    scatter_kernel<<<(n_edges + 255) / 256, 256>>>(src, dst, n_edges);
    agg_kernel<<<(n_nodes * 32 + 255) / 256, 256>>>(feat, bond, n_nodes);
    final_kernel<<<(n_nodes + 255) / 256, 256>>>(w_s, w_n, out, n_nodes);
}

// round 6
// speedup vs baseline: 1.0925x; 1.0925x over previous
#include <cuda_runtime.h>

// RuleGraphConvLayer — GB300 sm_103a, round 6
//
//   x[n] = [feat(81) | G + c*feat*(k>=3)(81) | bagg(22)]  (packed by agg)
//   out[n] = x[n] @ [w_s ; w_n]   (K=184, N=64)
//
// R6: revert final GEMM to the R4 broadcast form (R5 re-tile regressed).
// Collapse hist_zero+scan1+scan2+scan3 into one chained-prefix scan kernel
// that also re-zeroes g_hist for the next graph replay. 5 launches total
// (~4us fixed cost per launch observed).

#define MAX_NODES 100000
#define MAX_EDGES 800000
#define NF 81
#define NB 22
#define OC 64
#define KTOT 184
#define XP 188     // x row pitch: 752 B, every row 16B-aligned

#define SCAN_T 1024
#define SCAN_E 4
#define SCAN_B (SCAN_T * SCAN_E)

__device__ __align__(16) float g_x[MAX_NODES * XP];
__device__ int g_hist[MAX_NODES];          // zero at load; scan re-zeroes each call
__device__ int g_start[MAX_NODES + 1];
__device__ int g_cursor[MAX_NODES];
__device__ __align__(8) int2 g_sorted[MAX_EDGES];
__device__ volatile int g_ready;           // chained-scan turn counter (0 at load; reset each call)
__device__ volatile int g_running;         // running prefix (0 at load; reset each call)

// ---------------------------------------------------------------------------
// K1: histogram of src (g_hist is guaranteed zero on entry)
// ---------------------------------------------------------------------------
__global__ void hist_kernel(const int* __restrict__ src, int n_edges) {
    int e = blockIdx.x * blockDim.x + threadIdx.x;
    if (e < n_edges) atomicAdd(&g_hist[src[e]], 1);
}

// ---------------------------------------------------------------------------
// K2: single-pass chained exclusive scan over g_hist.
//   - per-block scan of 4096 elems
//   - blocks publish running total in bid order via g_ready turn counter
//     (25 blocks, all co-resident -> no deadlock)
//   - writes g_start + g_cursor, zeroes g_hist, caps g_start[n]
//   - last block resets g_ready/g_running to 0 => deterministic graph replay
// ---------------------------------------------------------------------------
__global__ __launch_bounds__(SCAN_T) void scan_chained_kernel(int n, int n_edges) {
    __shared__ int wsum[32];
    __shared__ int sbase;
    int t = threadIdx.x;
    int bid = blockIdx.x;
    int base = bid * SCAN_B + t * SCAN_E;

    int v[SCAN_E];
    int local = 0;
    #pragma unroll
    for (int j = 0; j < SCAN_E; j++) {
        v[j] = (base + j < n) ? g_hist[base + j] : 0;
        local += v[j];
    }
    int lane = t & 31, w = t >> 5;
    int inc = local;
    #pragma unroll
    for (int d = 1; d < 32; d <<= 1) {
        int x = __shfl_up_sync(0xFFFFFFFF, inc, d);
        if (lane >= d) inc += x;
    }
    if (lane == 31) wsum[w] = inc;
    __syncthreads();
    if (t < 32) {
        int x = wsum[t];
        #pragma unroll
        for (int d = 1; d < 32; d <<= 1) {
            int y = __shfl_up_sync(0xFFFFFFFF, x, d);
            if (t >= d) x += y;
        }
        wsum[t] = x;
    }
    __syncthreads();
    int excl = inc - local + ((w > 0) ? wsum[w - 1] : 0);   // within-block exclusive
    int block_total = wsum[31];

    // chained publish (thread 0)
    if (t == 0) {
        while (g_ready != bid) { }          // co-resident blocks -> bounded spin
        __threadfence();
        int b = g_running;
        sbase = b;
        bool last = (bid == (int)gridDim.x - 1);
        g_running = last ? 0 : (b + block_total);
        __threadfence();
        g_ready = last ? 0 : (bid + 1);
    }
    __syncthreads();
    int run = excl + sbase;

    #pragma unroll
    for (int j = 0; j < SCAN_E; j++) {
        int i = base + j;
        if (i < n) {
            g_start[i] = run;
            g_cursor[i] = run;
            g_hist[i] = 0;                   // ready for next replay
            run += v[j];
        }
    }
    if (bid == (int)gridDim.x - 1 && t == SCAN_T - 1) g_start[n] = n_edges;
}

// ---------------------------------------------------------------------------
// K3: scatter edges into per-src contiguous lists
// ---------------------------------------------------------------------------
__global__ void scatter_kernel(const int* __restrict__ src,
                               const int* __restrict__ dst,
                               int n_edges) {
    int e = blockIdx.x * blockDim.x + threadIdx.x;
    if (e >= n_edges) return;
    int s = src[e];
    int pos = atomicAdd(&g_cursor[s], 1);
    g_sorted[pos] = make_int2(dst[e], e);
}

// ---------------------------------------------------------------------------
// K4: agg — warp per node; gathers feat[dst]/bond, reduces in registers,
// writes the fully-packed x row. 2-edge software pipeline.
// ---------------------------------------------------------------------------
__global__ __launch_bounds__(256) void agg_kernel(
    const float* __restrict__ feat,
    const float* __restrict__ bond,
    int n_nodes) {

    int n = (int)((blockIdx.x * 256 + threadIdx.x) >> 5);
    int lane = threadIdx.x & 31;
    if (n >= n_nodes) return;

    int beg = __ldg(g_start + n);
    int end = __ldg(g_start + n + 1);

    const float* fs = feat + (size_t)n * NF;
    bool has2 = (lane < NF - 64);   // lane < 17
    bool hasb = (lane < NB);
    float f0 = __ldg(fs + lane);
    float f1 = __ldg(fs + lane + 32);
    float f2 = has2 ? __ldg(fs + lane + 64) : 0.f;
    float fs0 = __shfl_sync(0xFFFFFFFF, f0, 0);
    float fs1 = __shfl_sync(0xFFFFFFFF, f0, 1);
    float fs2 = __shfl_sync(0xFFFFFFFF, f0, 2);

    float a0 = 0.f, a1 = 0.f, a2 = 0.f, ab = 0.f, ac = 0.f;

    int i = beg;
    for (; i + 1 < end; i += 2) {
        int2 p0 = __ldg(g_sorted + i);
        int2 p1 = __ldg(g_sorted + i + 1);
        const float* fdA = feat + (size_t)p0.x * NF;
        const float* fdB = feat + (size_t)p1.x * NF;
        float u0 = __ldg(fdA + lane);
        float w0 = __ldg(fdB + lane);
        float u1 = __ldg(fdA + lane + 32);
        float w1 = __ldg(fdB + lane + 32);
        float u2 = has2 ? __ldg(fdA + lane + 64) : 0.f;
        float w2 = has2 ? __ldg(fdB + lane + 64) : 0.f;
        float bu = hasb ? __ldg(bond + (size_t)p0.y * NB + lane) : 0.f;
        float bw = hasb ? __ldg(bond + (size_t)p1.y * NB + lane) : 0.f;

        float dxA = fs0 - __shfl_sync(0xFFFFFFFF, u0, 0);
        float dyA = fs1 - __shfl_sync(0xFFFFFFFF, u0, 1);
        float dzA = fs2 - __shfl_sync(0xFFFFFFFF, u0, 2);
        float ddA = dxA * dxA + dyA * dyA + dzA * dzA;
        float sA = (ddA > 0.f) ? (1.f / ddA) : 10000.f;

        float dxB = fs0 - __shfl_sync(0xFFFFFFFF, w0, 0);
        float dyB = fs1 - __shfl_sync(0xFFFFFFFF, w0, 1);
        float dzB = fs2 - __shfl_sync(0xFFFFFFFF, w0, 2);
        float ddB = dxB * dxB + dyB * dyB + dzB * dzB;
        float sB = (ddB > 0.f) ? (1.f / ddB) : 10000.f;

        a0 += sA * u0 + sB * w0;
        a1 += sA * u1 + sB * w1;
        a2 += sA * u2 + sB * w2;
        ab += bu + bw;
        ac += sA + sB;
    }
    if (i < end) {
        int2 p0 = __ldg(g_sorted + i);
        const float* fdA = feat + (size_t)p0.x * NF;
        float u0 = __ldg(fdA + lane);
        float u1 = __ldg(fdA + lane + 32);
        float u2 = has2 ? __ldg(fdA + lane + 64) : 0.f;
        float bu = hasb ? __ldg(bond + (size_t)p0.y * NB + lane) : 0.f;
        float dxA = fs0 - __shfl_sync(0xFFFFFFFF, u0, 0);
        float dyA = fs1 - __shfl_sync(0xFFFFFFFF, u0, 1);
        float dzA = fs2 - __shfl_sync(0xFFFFFFFF, u0, 2);
        float ddA = dxA * dxA + dyA * dyA + dzA * dzA;
        float sA = (ddA > 0.f) ? (1.f / ddA) : 10000.f;
        a0 += sA * u0;
        a1 += sA * u1;
        a2 += sA * u2;
        ab += bu;
        ac += sA;
    }

    float* xr = g_x + (size_t)n * XP;
    xr[lane] = f0;
    xr[lane + 32] = f1;
    if (has2) xr[lane + 64] = f2;
    xr[NF + lane]      = (lane >= 3) ? (a0 + ac * f0) : a0;
    xr[NF + lane + 32] = a1 + ac * f1;
    if (has2) xr[NF + lane + 64] = a2 + ac * f2;
    if (hasb) xr[2 * NF + lane] = ab;
}

// ---------------------------------------------------------------------------
// K5: final GEMM (R4 form). One node per thread, 64 ch as 32 packed f32x2
// accs, x via LDG.128, W broadcast from smem via LDS.128, FFMA2.
// ---------------------------------------------------------------------------
__device__ __forceinline__ void fma2_step(unsigned long long* acc,
                                          const float* wrow, float xv) {
    unsigned long long xx;
    asm("mov.b64 %0, {%1, %1};" : "=l"(xx) : "f"(xv));
    const ulonglong2* w2 = reinterpret_cast<const ulonglong2*>(wrow);
    #pragma unroll
    for (int j = 0; j < 16; j++) {
        ulonglong2 wv = w2[j];
        asm("fma.rn.f32x2 %0, %1, %2, %0;" : "+l"(acc[2 * j + 0]) : "l"(xx), "l"(wv.x));
        asm("fma.rn.f32x2 %0, %1, %2, %0;" : "+l"(acc[2 * j + 1]) : "l"(xx), "l"(wv.y));
    }
}

__global__ __launch_bounds__(256) void final_kernel(
    const float* __restrict__ w_s,   // [81][64]
    const float* __restrict__ w_n,   // [103][64]
    float* __restrict__ out,         // [n_nodes][64]
    int n_nodes) {

    __shared__ __align__(16) float Wsh[KTOT * OC];   // 47104 B

    int tid = threadIdx.x;
    int node = blockIdx.x * 256 + tid;

    #pragma unroll
    for (int r = 0; r < 46; r++) {                   // 46*256 == 184*64
        int idx = r * 256 + tid;
        int k = idx >> 6;
        int c = idx & (OC - 1);
        Wsh[idx] = (k < NF) ? __ldg(w_s + k * OC + c)
                            : __ldg(w_n + (k - NF) * OC + c);
    }
    __syncthreads();

    if (node >= n_nodes) return;

    const float4* xrow = reinterpret_cast<const float4*>(g_x + (size_t)node * XP);

    unsigned long long acc[32];
    #pragma unroll
    for (int j = 0; j < 32; j++) acc[j] = 0ull;

    float4 xv = __ldg(xrow);               // prefetch
    const float* wp = Wsh;
    #pragma unroll 2
    for (int k4 = 0; k4 < 46; k4++) {
        float4 cur = xv;
        if (k4 + 1 < 46) xv = __ldg(xrow + k4 + 1);
        fma2_step(acc, wp,          cur.x);
        fma2_step(acc, wp + OC,     cur.y);
        fma2_step(acc, wp + 2 * OC, cur.z);
        fma2_step(acc, wp + 3 * OC, cur.w);
        wp += 4 * OC;
    }

    float* orow = out + (size_t)node * OC;
    #pragma unroll
    for (int j = 0; j < 16; j++) {
        float x0, x1, x2, x3;
        asm("mov.b64 {%0, %1}, %2;" : "=f"(x0), "=f"(x1) : "l"(acc[2 * j + 0]));
        asm("mov.b64 {%0, %1}, %2;" : "=f"(x2), "=f"(x3) : "l"(acc[2 * j + 1]));
        reinterpret_cast<float4*>(orow)[j] = make_float4(x0, x1, x2, x3);
    }
}

// ---------------------------------------------------------------------------
extern "C" void kernel_launch(void* const* d_in, const int* in_sizes, int n_in,
                              void* d_out, int out_size) {
    const float* feat = (const float*)d_in[0];
    const float* bond = (const float*)d_in[1];
    const float* w_s  = (const float*)d_in[2];
    const float* w_n  = (const float*)d_in[3];
    const int*   src  = (const int*)d_in[4];
    const int*   dst  = (const int*)d_in[5];
    float* out = (float*)d_out;

    int n_nodes = in_sizes[0] / NF;
    int n_edges = in_sizes[4];
    int nsb = (n_nodes + SCAN_B - 1) / SCAN_B;   // 25 blocks for 100K nodes

    hist_kernel<<<(n_edges + 255) / 256, 256>>>(src, n_edges);
    scan_chained_kernel<<<nsb, SCAN_T>>>(n_nodes, n_edges);
    scatter_kernel<<<(n_edges + 255) / 256, 256>>>(src, dst, n_edges);
    agg_kernel<<<(n_nodes * 32 + 255) / 256, 256>>>(feat, bond, n_nodes);
    final_kernel<<<(n_nodes + 255) / 256, 256>>>(w_s, w_n, out, n_nodes);
}

// round 7
// speedup vs baseline: 1.3197x; 1.2080x over previous
#include <cuda_runtime.h>

// RuleGraphConvLayer — GB300 sm_103a, round 7
//
//   x[n] = [feat(81) | G + c*feat*(k>=3)(81) | bagg(22)]  (packed by agg)
//   out[n] = x[n] @ [w_s ; w_n]   (K=184, N=64)
//
// R7 vs best (R4, 238us):
//   * agg: SHFL coord-extraction replaced by warp-uniform broadcast loads;
//     4-edge software pipeline (28 loads in flight); __frcp_rn.
//   * scan: R4's proven multi-kernel structure; scan1 self-zeroes g_hist
//     (hist_zero launch dropped); scan2+scan3 folded (worked in R5/R6).
//   * final GEMM: R4 form unchanged (broadcast W + FFMA2).

#define MAX_NODES 100000
#define MAX_EDGES 800000
#define NF 81
#define NB 22
#define OC 64
#define KTOT 184
#define XP 188     // x row pitch: 752 B, every row 16B-aligned

#define SCAN_T 1024
#define SCAN_E 4
#define SCAN_B (SCAN_T * SCAN_E)

__device__ __align__(16) float g_x[MAX_NODES * XP];
__device__ int g_hist[MAX_NODES];          // zero at load; scan1 re-zeroes after reading
__device__ int g_start[MAX_NODES + 1];
__device__ int g_cursor[MAX_NODES];
__device__ int g_bsum[64];
__device__ __align__(8) int2 g_sorted[MAX_EDGES];

// ---------------------------------------------------------------------------
// K1: histogram of src (g_hist guaranteed zero on entry)
// ---------------------------------------------------------------------------
__global__ void hist_kernel(const int* __restrict__ src, int n_edges) {
    int e = blockIdx.x * blockDim.x + threadIdx.x;
    if (e < n_edges) atomicAdd(&g_hist[src[e]], 1);
}

// ---------------------------------------------------------------------------
// K2: per-block exclusive scan over 4096 elems; totals to g_bsum.
// Re-zeroes g_hist after reading (each element read by exactly one thread).
// ---------------------------------------------------------------------------
__global__ __launch_bounds__(SCAN_T) void scan1_kernel(int n) {
    __shared__ int wsum[32];
    int t = threadIdx.x;
    int base = blockIdx.x * SCAN_B + t * SCAN_E;
    int v[SCAN_E];
    int local = 0;
    #pragma unroll
    for (int j = 0; j < SCAN_E; j++) {
        int i = base + j;
        v[j] = (i < n) ? g_hist[i] : 0;
        if (i < n) g_hist[i] = 0;          // ready for next graph replay
        local += v[j];
    }
    int lane = t & 31, w = t >> 5;
    int inc = local;
    #pragma unroll
    for (int d = 1; d < 32; d <<= 1) {
        int x = __shfl_up_sync(0xFFFFFFFF, inc, d);
        if (lane >= d) inc += x;
    }
    if (lane == 31) wsum[w] = inc;
    __syncthreads();
    if (t < 32) {
        int x = wsum[t];
        #pragma unroll
        for (int d = 1; d < 32; d <<= 1) {
            int y = __shfl_up_sync(0xFFFFFFFF, x, d);
            if (t >= d) x += y;
        }
        wsum[t] = x;
    }
    __syncthreads();
    int run = inc - local + ((w > 0) ? wsum[w - 1] : 0);
    #pragma unroll
    for (int j = 0; j < SCAN_E; j++) {
        if (base + j < n) g_start[base + j] = run;
        run += v[j];
    }
    if (t == SCAN_T - 1) g_bsum[blockIdx.x] = run;
}

// ---------------------------------------------------------------------------
// K3: scan block sums (redundantly per block) + apply offsets + init cursors
// ---------------------------------------------------------------------------
__global__ __launch_bounds__(256) void scan23_kernel(int n, int n_edges, int nsb) {
    __shared__ int off[32];
    int t = threadIdx.x;
    if (t < 32) {
        int x = (t < nsb) ? g_bsum[t] : 0;
        int inc = x;
        #pragma unroll
        for (int d = 1; d < 32; d <<= 1) {
            int y = __shfl_up_sync(0xFFFFFFFF, inc, d);
            if (t >= d) inc += y;
        }
        off[t] = inc - x;   // exclusive
    }
    __syncthreads();
    int i = blockIdx.x * 256 + t;
    if (i < n) {
        int v = g_start[i] + off[i / SCAN_B];
        g_start[i] = v;
        g_cursor[i] = v;
    }
    if (i == 0) g_start[n] = n_edges;
}

// ---------------------------------------------------------------------------
// K4: scatter edges into per-src contiguous lists
// ---------------------------------------------------------------------------
__global__ void scatter_kernel(const int* __restrict__ src,
                               const int* __restrict__ dst,
                               int n_edges) {
    int e = blockIdx.x * blockDim.x + threadIdx.x;
    if (e >= n_edges) return;
    int s = src[e];
    int pos = atomicAdd(&g_cursor[s], 1);
    g_sorted[pos] = make_int2(dst[e], e);
}

// ---------------------------------------------------------------------------
// K5: agg — warp per node. No SHFLs: dst coords via warp-uniform broadcast
// loads. 4-edge pipeline (28 independent loads in flight). Writes packed x.
// ---------------------------------------------------------------------------
__global__ __launch_bounds__(256) void agg_kernel(
    const float* __restrict__ feat,
    const float* __restrict__ bond,
    int n_nodes) {

    int n = (int)((blockIdx.x * 256 + threadIdx.x) >> 5);
    int lane = threadIdx.x & 31;
    if (n >= n_nodes) return;

    int beg = __ldg(g_start + n);
    int end = __ldg(g_start + n + 1);

    const float* fs = feat + (size_t)n * NF;
    bool has2 = (lane < NF - 64);   // lane < 17
    bool hasb = (lane < NB);
    float f0 = __ldg(fs + lane);
    float f1 = __ldg(fs + lane + 32);
    float f2 = has2 ? __ldg(fs + lane + 64) : 0.f;
    float fs0 = __ldg(fs + 0), fs1 = __ldg(fs + 1), fs2 = __ldg(fs + 2);

    float a0 = 0.f, a1 = 0.f, a2 = 0.f, ab = 0.f, ac = 0.f;

    int i = beg;
    for (; i + 3 < end; i += 4) {
        float u0[4], u1[4], u2[4], bv[4], c0[4], c1[4], c2[4];
        #pragma unroll
        for (int j = 0; j < 4; j++) {
            int2 p = __ldg(g_sorted + i + j);
            const float* fd = feat + (size_t)p.x * NF;
            c0[j] = __ldg(fd + 0);            // warp-uniform -> broadcast
            c1[j] = __ldg(fd + 1);
            c2[j] = __ldg(fd + 2);
            u0[j] = __ldg(fd + lane);
            u1[j] = __ldg(fd + lane + 32);
            u2[j] = has2 ? __ldg(fd + lane + 64) : 0.f;
            bv[j] = hasb ? __ldg(bond + (size_t)p.y * NB + lane) : 0.f;
        }
        #pragma unroll
        for (int j = 0; j < 4; j++) {
            float dx = fs0 - c0[j], dy = fs1 - c1[j], dz = fs2 - c2[j];
            float dd = dx * dx + dy * dy + dz * dz;
            float s = (dd > 0.f) ? __frcp_rn(dd) : 10000.f;
            a0 += s * u0[j];
            a1 += s * u1[j];
            a2 += s * u2[j];
            ab += bv[j];
            ac += s;
        }
    }
    for (; i < end; i++) {
        int2 p = __ldg(g_sorted + i);
        const float* fd = feat + (size_t)p.x * NF;
        float c0 = __ldg(fd + 0), c1 = __ldg(fd + 1), c2 = __ldg(fd + 2);
        float u0 = __ldg(fd + lane);
        float u1 = __ldg(fd + lane + 32);
        float u2 = has2 ? __ldg(fd + lane + 64) : 0.f;
        float bv = hasb ? __ldg(bond + (size_t)p.y * NB + lane) : 0.f;
        float dx = fs0 - c0, dy = fs1 - c1, dz = fs2 - c2;
        float dd = dx * dx + dy * dy + dz * dz;
        float s = (dd > 0.f) ? __frcp_rn(dd) : 10000.f;
        a0 += s * u0;
        a1 += s * u1;
        a2 += s * u2;
        ab += bv;
        ac += s;
    }

    float* xr = g_x + (size_t)n * XP;
    xr[lane] = f0;
    xr[lane + 32] = f1;
    if (has2) xr[lane + 64] = f2;
    xr[NF + lane]      = (lane >= 3) ? (a0 + ac * f0) : a0;
    xr[NF + lane + 32] = a1 + ac * f1;
    if (has2) xr[NF + lane + 64] = a2 + ac * f2;
    if (hasb) xr[2 * NF + lane] = ab;
}

// ---------------------------------------------------------------------------
// K6: final GEMM (R4 form, unchanged). One node per thread, 32 f32x2 accs,
// x via LDG.128, W broadcast from smem via LDS.128, FFMA2.
// ---------------------------------------------------------------------------
__device__ __forceinline__ void fma2_step(unsigned long long* acc,
                                          const float* wrow, float xv) {
    unsigned long long xx;
    asm("mov.b64 %0, {%1, %1};" : "=l"(xx) : "f"(xv));
    const ulonglong2* w2 = reinterpret_cast<const ulonglong2*>(wrow);
    #pragma unroll
    for (int j = 0; j < 16; j++) {
        ulonglong2 wv = w2[j];
        asm("fma.rn.f32x2 %0, %1, %2, %0;" : "+l"(acc[2 * j + 0]) : "l"(xx), "l"(wv.x));
        asm("fma.rn.f32x2 %0, %1, %2, %0;" : "+l"(acc[2 * j + 1]) : "l"(xx), "l"(wv.y));
    }
}

__global__ __launch_bounds__(256) void final_kernel(
    const float* __restrict__ w_s,   // [81][64]
    const float* __restrict__ w_n,   // [103][64]
    float* __restrict__ out,         // [n_nodes][64]
    int n_nodes) {

    __shared__ __align__(16) float Wsh[KTOT * OC];   // 47104 B

    int tid = threadIdx.x;
    int node = blockIdx.x * 256 + tid;

    #pragma unroll
    for (int r = 0; r < 46; r++) {                   // 46*256 == 184*64
        int idx = r * 256 + tid;
        int k = idx >> 6;
        int c = idx & (OC - 1);
        Wsh[idx] = (k < NF) ? __ldg(w_s + k * OC + c)
                            : __ldg(w_n + (k - NF) * OC + c);
    }
    __syncthreads();

    if (node >= n_nodes) return;

    const float4* xrow = reinterpret_cast<const float4*>(g_x + (size_t)node * XP);

    unsigned long long acc[32];
    #pragma unroll
    for (int j = 0; j < 32; j++) acc[j] = 0ull;

    float4 xv = __ldg(xrow);               // prefetch
    const float* wp = Wsh;
    #pragma unroll 2
    for (int k4 = 0; k4 < 46; k4++) {
        float4 cur = xv;
        if (k4 + 1 < 46) xv = __ldg(xrow + k4 + 1);
        fma2_step(acc, wp,          cur.x);
        fma2_step(acc, wp + OC,     cur.y);
        fma2_step(acc, wp + 2 * OC, cur.z);
        fma2_step(acc, wp + 3 * OC, cur.w);
        wp += 4 * OC;
    }

    float* orow = out + (size_t)node * OC;
    #pragma unroll
    for (int j = 0; j < 16; j++) {
        float x0, x1, x2, x3;
        asm("mov.b64 {%0, %1}, %2;" : "=f"(x0), "=f"(x1) : "l"(acc[2 * j + 0]));
        asm("mov.b64 {%0, %1}, %2;" : "=f"(x2), "=f"(x3) : "l"(acc[2 * j + 1]));
        reinterpret_cast<float4*>(orow)[j] = make_float4(x0, x1, x2, x3);
    }
}

// ---------------------------------------------------------------------------
extern "C" void kernel_launch(void* const* d_in, const int* in_sizes, int n_in,
                              void* d_out, int out_size) {
    const float* feat = (const float*)d_in[0];
    const float* bond = (const float*)d_in[1];
    const float* w_s  = (const float*)d_in[2];
    const float* w_n  = (const float*)d_in[3];
    const int*   src  = (const int*)d_in[4];
    const int*   dst  = (const int*)d_in[5];
    float* out = (float*)d_out;

    int n_nodes = in_sizes[0] / NF;
    int n_edges = in_sizes[4];
    int nsb = (n_nodes + SCAN_B - 1) / SCAN_B;   // 25 blocks for 100K nodes

    hist_kernel<<<(n_edges + 255) / 256, 256>>>(src, n_edges);
    scan1_kernel<<<nsb, SCAN_T>>>(n_nodes);
    scan23_kernel<<<(n_nodes + 255) / 256, 256>>>(n_nodes, n_edges, nsb);
    scatter_kernel<<<(n_edges + 255) / 256, 256>>>(src, dst, n_edges);
    agg_kernel<<<(n_nodes * 32 + 255) / 256, 256>>>(feat, bond, n_nodes);
    final_kernel<<<(n_nodes + 255) / 256, 256>>>(w_s, w_n, out, n_nodes);
}